// round 16
// baseline (speedup 1.0000x reference)
#include <cuda_runtime.h>
#include <math.h>

#define Bsz  32
#define Tlen 512
#define Idim 1024
#define Hdim 1024
#define G4   4096
#define NBLK 128

// ---------------- device scratch ----------------
__device__ float g_xw[(size_t)Tlen * Bsz * G4];       // [t][b][4H]
// A fragment-major: [MT 1024][KT 128][lane 32] x float4
__device__ float4 g_xa[(size_t)1024 * 128 * 32];
// B (W_ih) fragment-major: [NT 512][KT2 64][lane 32] x float4
__device__ float4 g_wb[(size_t)512 * 64 * 32];
__device__ float g_hA[2][2][128][32][4];              // h A-frag layout (tf32 bits)
__device__ unsigned int g_bar;

// ---------------- helpers ----------------
__device__ __forceinline__ unsigned f2tf32(float f)
{
    unsigned r;
    asm("cvt.rna.tf32.f32 %0, %1;" : "=r"(r) : "f"(f));
    return r;
}
__device__ __forceinline__ void mma_tf32(float* d, const unsigned* a, const unsigned* b)
{
    asm volatile(
        "mma.sync.aligned.m16n8k8.row.col.f32.tf32.tf32.f32 "
        "{%0,%1,%2,%3},{%4,%5,%6,%7},{%8,%9},{%0,%1,%2,%3};"
        : "+f"(d[0]), "+f"(d[1]), "+f"(d[2]), "+f"(d[3])
        : "r"(a[0]), "r"(a[1]), "r"(a[2]), "r"(a[3]), "r"(b[0]), "r"(b[1]));
}
__device__ __forceinline__ uint4 lds128(unsigned addr)
{
    uint4 v;
    asm volatile("ld.shared.v4.b32 {%0,%1,%2,%3}, [%4];"
                 : "=r"(v.x), "=r"(v.y), "=r"(v.z), "=r"(v.w) : "r"(addr));
    return v;
}
__device__ __forceinline__ float sig_fast(float x)
{
    return __frcp_rn(1.f + __expf(-x));
}
__device__ __forceinline__ float tanh_fast(float x)
{
    return fmaf(2.f, __frcp_rn(1.f + __expf(-2.f * x)), -1.f);
}

// =======================================================================
// Kernel 0: build fragment-major tf32-rounded copies of x and W_ih.
// =======================================================================
__global__ void __launch_bounds__(256) prep_kernel(
    const float* __restrict__ x, const float* __restrict__ Wih)
{
    if (blockIdx.x == 0 && threadIdx.x == 0) g_bar = 0u;
    const size_t NA = (size_t)1024 * 128 * 32;
    const size_t NW = (size_t)512 * 64 * 32;
    size_t i0 = (size_t)blockIdx.x * blockDim.x + threadIdx.x;
    size_t stride = (size_t)gridDim.x * blockDim.x;

    for (size_t i = i0; i < NA; i += stride) {
        int l  = (int)(i & 31);
        int KT = (int)((i >> 5) & 127);
        int MT = (int)(i >> 12);
        int g = l >> 2, tg = l & 3;
        const float* base = x + (size_t)(MT * 16 + g) * Idim + KT * 8 + tg;
        uint4 r;
        r.x = f2tf32(base[0]);
        r.y = f2tf32(base[8 * Idim]);
        r.z = f2tf32(base[4]);
        r.w = f2tf32(base[8 * Idim + 4]);
        *(uint4*)&g_xa[i] = r;
    }
    for (size_t i = i0; i < NW; i += stride) {
        int l   = (int)(i & 31);
        int KT2 = (int)((i >> 5) & 63);
        int NT  = (int)(i >> 11);
        int g = l >> 2, tg = l & 3;
        const float* base = Wih + (size_t)(NT * 8 + g) * Idim + KT2 * 16 + tg;
        uint4 r;
        r.x = f2tf32(base[0]);
        r.y = f2tf32(base[4]);
        r.z = f2tf32(base[8]);
        r.w = f2tf32(base[12]);
        *(uint4*)&g_wb[i] = r;
    }
}

// =======================================================================
// Phase 1: g_xw = x @ Wih^T + b. Persistent N-slice design, NO syncs in
// the main loop. 128 blocks x 256 thr (8 warps). Block owns N=32 (4 n8
// tiles); W fragments resident in smem (128 KB, loaded once). 128 M-chunks
// of 128 rows; warp wi owns m-tile MT = chunk*8+wi. A fragments streamed
// from fragment-major global via __ldcg, prefetched 1 kt2 ahead.
// =======================================================================
#define P1_SMEM (4 * 64 * 32 * 16)     // 131072 bytes

__global__ void __launch_bounds__(256, 1) gemm_xw_kernel(const float* __restrict__ bias)
{
    extern __shared__ float sm[];      // [nt 4][kt2 64][lane 32] x float4

    const int tid  = threadIdx.x;
    const int wi   = tid >> 5;         // 0..7
    const int lane = tid & 31;
    const int g    = lane >> 2;
    const int tg   = lane & 3;

    const int bid = blockIdx.x;        // 0..127
    const int bn  = bid * 32;
    const int NT0 = bid * 4;

    // ---- one-time: W fragments into smem ----
    for (int idx = tid; idx < 4 * 64 * 32; idx += 256) {
        int l   = idx & 31;
        int kt2 = (idx >> 5) & 63;
        int nt  = idx >> 11;
        *(float4*)&sm[(size_t)idx * 4] =
            g_wb[((size_t)(NT0 + nt) * 64 + kt2) * 32 + l];
    }
    __syncthreads();                    // the only sync in this kernel

    const unsigned smb = (unsigned)__cvta_generic_to_shared(sm);

    float2 bv[4];
#pragma unroll
    for (int nt = 0; nt < 4; nt++) {
        int j0 = bn + nt * 8 + tg * 2;
        bv[nt].x = __ldg(bias + j0);
        bv[nt].y = __ldg(bias + j0 + 1);
    }

    for (int chunk = 0; chunk < 128; chunk++) {
        const int MT = chunk * 8 + wi;
        const uint4* Ap = (const uint4*)g_xa + ((size_t)MT * 128) * 32 + lane;

        float D[4][4];
#pragma unroll
        for (int nt = 0; nt < 4; nt++)
#pragma unroll
            for (int q = 0; q < 4; q++) D[nt][q] = 0.f;

        uint4 a0 = __ldcg(Ap);
        uint4 a1 = __ldcg(Ap + 32);
#pragma unroll 4
        for (int kt2 = 0; kt2 < 64; kt2++) {
            uint4 c0 = a0, c1 = a1;
            if (kt2 < 63) {
                a0 = __ldcg(Ap + (2 * kt2 + 2) * 32);
                a1 = __ldcg(Ap + (2 * kt2 + 3) * 32);
            }
#pragma unroll
            for (int nt = 0; nt < 4; nt++) {
                uint4 Bp = lds128(smb + (unsigned)(((nt * 64 + kt2) * 32 + lane) * 16));
                unsigned bf0[2], bf1[2];
                bf0[0] = Bp.x; bf0[1] = Bp.y;
                bf1[0] = Bp.z; bf1[1] = Bp.w;
                mma_tf32(D[nt], (const unsigned*)&c0, bf0);
                mma_tf32(D[nt], (const unsigned*)&c1, bf1);
            }
        }

        // ---- epilogue for this chunk: +bias, scatter to g_xw[t][b][n] ----
        int r0 = MT * 16 + g;
        int r1 = r0 + 8;
        int t0 = r0 & (Tlen - 1), b0 = r0 >> 9;
        int t1 = r1 & (Tlen - 1), b1 = r1 >> 9;
        float* base0 = &g_xw[(size_t)t0 * (Bsz * G4) + (size_t)b0 * G4];
        float* base1 = &g_xw[(size_t)t1 * (Bsz * G4) + (size_t)b1 * G4];
#pragma unroll
        for (int nt = 0; nt < 4; nt++) {
            int j0 = bn + nt * 8 + tg * 2;
            float2 v0; v0.x = D[nt][0] + bv[nt].x; v0.y = D[nt][1] + bv[nt].y;
            float2 v1; v1.x = D[nt][2] + bv[nt].x; v1.y = D[nt][3] + bv[nt].y;
            *(float2*)(base0 + j0) = v0;
            *(float2*)(base1 + j0) = v1;
        }
    }
}

// =======================================================================
// Phase 2: persistent tensor-core recurrence (VERBATIM best — at floor).
// =======================================================================
#define SWB_FLOATS (4 * 128 * 32 * 2)           // 32768 (128 KB)
#define SPART_FLOATS (8 * 2 * 4 * 32 * 4)       // 4096  (16 KB)
#define SMEM_P2 ((SWB_FLOATS + SPART_FLOATS) * 4)

__device__ __forceinline__ void grid_barrier(unsigned target)
{
    __syncthreads();
    if (threadIdx.x == 0) {
        __threadfence();
        asm volatile("red.release.gpu.global.add.u32 [%0], %1;"
                     :: "l"(&g_bar), "r"(1u) : "memory");
        unsigned v;
        do {
            asm volatile("ld.acquire.gpu.global.u32 %0, [%1];"
                         : "=r"(v) : "l"(&g_bar) : "memory");
        } while (v < target);
    }
    __syncthreads();
}

__global__ void __launch_bounds__(256, 1) lstm_rec_kernel(
    const float* __restrict__ Whh, float* __restrict__ out)
{
    extern __shared__ float smemf[];
    float* sWB   = smemf;                // [g][kt][lane][2] tf32 B fragments
    float* sPart = smemf + SWB_FLOATS;   // [wi][mt][g][lane][4] fp32 partial D

    const int tid  = threadIdx.x;
    const int bid  = blockIdx.x;
    const int wi   = tid >> 5;
    const int lane = tid & 31;

    for (int idx = tid; idx < 4 * 128 * 32; idx += 256) {
        int l  = idx & 31;
        int kt = (idx >> 5) & 127;
        int g  = idx >> 12;
        int row = g * 1024 + bid * 8 + (l >> 2);
        int k0  = kt * 8 + (l & 3);
        unsigned* dst = (unsigned*)&sWB[((g * 128 + kt) * 32 + l) * 2];
        dst[0] = f2tf32(Whh[(size_t)row * Hdim + k0]);
        dst[1] = f2tf32(Whh[(size_t)row * Hdim + k0 + 4]);
    }

    const int rb = tid >> 3;
    const int rh = tid & 7;
    const int j  = bid * 8 + rh;

    const int p_mt   = rb >> 4;
    const int p_kt   = j >> 3;
    const int p_lane = (rb & 7) * 4 + (rh & 3);
    const int p_reg  = ((rb & 15) >> 3) + 2 * (rh >> 2);

    g_hA[0][p_mt][p_kt][p_lane][p_reg] = 0.f;

    const int laneD = (rb & 7) * 4 + (rh >> 1);
    const int regD  = (rh & 1) + 2 * ((rb & 15) >> 3);
    const int mtD   = rb >> 4;

    const float* xwp = g_xw + (size_t)rb * G4 + j;
    float xv[4];
#pragma unroll
    for (int g = 0; g < 4; g++) xv[g] = __ldg(xwp + g * 1024);

    float c_state = 0.f;
    unsigned target = NBLK;
    grid_barrier(target);

    const int kt0 = wi * 16;

    for (int t = 0; t < Tlen; t++) {
        const int rbuf = t & 1, wbuf = rbuf ^ 1;

        float D[2][4][4];
#pragma unroll
        for (int m = 0; m < 2; m++)
#pragma unroll
            for (int n = 0; n < 4; n++)
#pragma unroll
                for (int q = 0; q < 4; q++) D[m][n][q] = 0.f;

        uint4 A0 = __ldcg((const uint4*)&g_hA[rbuf][0][kt0][lane][0]);
        uint4 A1 = __ldcg((const uint4*)&g_hA[rbuf][1][kt0][lane][0]);
#pragma unroll
        for (int i = 0; i < 16; i++) {
            uint4 a0 = A0, a1 = A1;
            if (i < 15) {
                A0 = __ldcg((const uint4*)&g_hA[rbuf][0][kt0 + i + 1][lane][0]);
                A1 = __ldcg((const uint4*)&g_hA[rbuf][1][kt0 + i + 1][lane][0]);
            }
#pragma unroll
            for (int g = 0; g < 4; g++) {
                unsigned bfrag[2];
                *(uint2*)bfrag = *(const uint2*)&sWB[((g * 128 + kt0 + i) * 32 + lane) * 2];
                mma_tf32(D[0][g], (const unsigned*)&a0, bfrag);
                mma_tf32(D[1][g], (const unsigned*)&a1, bfrag);
            }
        }

#pragma unroll
        for (int m = 0; m < 2; m++)
#pragma unroll
            for (int g = 0; g < 4; g++)
                *(float4*)&sPart[(((wi * 2 + m) * 4 + g) * 32 + lane) * 4] =
                    *(float4*)D[m][g];
        __syncthreads();

        float z[4];
#pragma unroll
        for (int g = 0; g < 4; g++) {
            float s = xv[g];
#pragma unroll
            for (int w = 0; w < 8; w++)
                s += sPart[(((w * 2 + mtD) * 4 + g) * 32 + laneD) * 4 + regD];
            z[g] = s;
        }

        float ig = sig_fast(z[0]);
        float fg = sig_fast(z[1]);
        float gg = tanh_fast(z[2]);
        float og = sig_fast(z[3]);
        c_state = fmaf(fg, c_state, ig * gg);
        float hv = og * tanh_fast(c_state);

        *(unsigned*)&g_hA[wbuf][p_mt][p_kt][p_lane][p_reg] = f2tf32(hv);
        out[((size_t)rb * Tlen + t) * Hdim + j] = hv;

        if (t + 1 < Tlen) {
            const float* nx = xwp + (size_t)(t + 1) * (Bsz * G4);
#pragma unroll
            for (int g = 0; g < 4; g++) xv[g] = __ldg(nx + g * 1024);
        }

        target += NBLK;
        grid_barrier(target);
    }
}

// =======================================================================
extern "C" void kernel_launch(void* const* d_in, const int* in_sizes, int n_in,
                              void* d_out, int out_size)
{
    const float* x    = (const float*)d_in[0];
    const float* Wih  = (const float*)d_in[1];
    const float* Whh  = (const float*)d_in[2];
    const float* bias = (const float*)d_in[3];
    float* out = (float*)d_out;

    cudaFuncSetAttribute(gemm_xw_kernel,
                         cudaFuncAttributeMaxDynamicSharedMemorySize, P1_SMEM);
    cudaFuncSetAttribute(lstm_rec_kernel,
                         cudaFuncAttributeMaxDynamicSharedMemorySize, SMEM_P2);

    prep_kernel<<<2048, 256>>>(x, Wih);

    gemm_xw_kernel<<<128, 256, P1_SMEM>>>(bias);

    lstm_rec_kernel<<<NBLK, 256, SMEM_P2>>>(Whh, out);
}

// round 17
// speedup vs baseline: 1.6520x; 1.6520x over previous
#include <cuda_runtime.h>
#include <cuda_fp16.h>
#include <math.h>

#define Bsz  32
#define Tlen 512
#define Idim 1024
#define Hdim 1024
#define G4   4096
#define NBLK 128

// ---------------- device scratch ----------------
__device__ float g_xw[(size_t)Tlen * Bsz * G4];       // [t][b][4H] fp32
// A fp16 fragments (m16n8k16): [MT 1024][KT16 64][lane 32] x uint4 (8 halves)
__device__ uint4 g_xa[(size_t)1024 * 64 * 32];
// B fp16 fragments: [NT 512][KT32 32][lane 32] x uint4 (.xy = kt16 even, .zw = odd)
__device__ uint4 g_wb[(size_t)512 * 32 * 32];
// h fp16 A-fragments: [buf 2][mt 2][kt16 64][lane 32] x uint4
__device__ uint4 g_hA[2][2][64][32];
__device__ unsigned int g_bar;

// ---------------- helpers ----------------
__device__ __forceinline__ unsigned pack_h2(float a, float b)
{
    __half2 h;
    h.x = __float2half_rn(a);
    h.y = __float2half_rn(b);
    return *(unsigned*)&h;
}
__device__ __forceinline__ void mma_f16(float* d, const unsigned* a, const unsigned* b)
{
    asm volatile(
        "mma.sync.aligned.m16n8k16.row.col.f32.f16.f16.f32 "
        "{%0,%1,%2,%3},{%4,%5,%6,%7},{%8,%9},{%0,%1,%2,%3};"
        : "+f"(d[0]), "+f"(d[1]), "+f"(d[2]), "+f"(d[3])
        : "r"(a[0]), "r"(a[1]), "r"(a[2]), "r"(a[3]), "r"(b[0]), "r"(b[1]));
}
__device__ __forceinline__ void cp_async16(unsigned dst, const void* src)
{
    asm volatile("cp.async.cg.shared.global [%0], [%1], 16;" :: "r"(dst), "l"(src));
}
#define CP_COMMIT()  asm volatile("cp.async.commit_group;")
#define CP_WAIT(N)   asm volatile("cp.async.wait_group %0;" :: "n"(N))

__device__ __forceinline__ uint4 lds128(unsigned addr)
{
    uint4 v;
    asm volatile("ld.shared.v4.b32 {%0,%1,%2,%3}, [%4];"
                 : "=r"(v.x), "=r"(v.y), "=r"(v.z), "=r"(v.w) : "r"(addr));
    return v;
}
__device__ __forceinline__ float sig_fast(float x)
{
    return __frcp_rn(1.f + __expf(-x));
}
__device__ __forceinline__ float tanh_fast(float x)
{
    return fmaf(2.f, __frcp_rn(1.f + __expf(-2.f * x)), -1.f);
}

// =======================================================================
// Kernel 0: build fp16 fragment-major copies of x and W_ih.
// =======================================================================
__global__ void __launch_bounds__(256) prep_kernel(
    const float* __restrict__ x, const float* __restrict__ Wih)
{
    if (blockIdx.x == 0 && threadIdx.x == 0) g_bar = 0u;
    const size_t NA = (size_t)1024 * 64 * 32;   // 2M
    const size_t NW = (size_t)512 * 32 * 32;    // 512K
    size_t i0 = (size_t)blockIdx.x * blockDim.x + threadIdx.x;
    size_t stride = (size_t)gridDim.x * blockDim.x;

    for (size_t i = i0; i < NA; i += stride) {
        int l  = (int)(i & 31);
        int KT = (int)((i >> 5) & 63);
        int MT = (int)(i >> 11);
        int g = l >> 2, tg = l & 3;
        const float* r0 = x + (size_t)(MT * 16 + g) * Idim + KT * 16 + tg * 2;
        const float* r1 = r0 + 8 * Idim;
        uint4 v;
        v.x = pack_h2(r0[0], r0[1]);
        v.y = pack_h2(r1[0], r1[1]);
        v.z = pack_h2(r0[8], r0[9]);
        v.w = pack_h2(r1[8], r1[9]);
        g_xa[i] = v;
    }
    for (size_t i = i0; i < NW; i += stride) {
        int l   = (int)(i & 31);
        int KT2 = (int)((i >> 5) & 31);
        int NT  = (int)(i >> 10);
        int g = l >> 2, tg = l & 3;
        const float* base = Wih + (size_t)(NT * 8 + g) * Idim + KT2 * 32 + tg * 2;
        uint4 v;
        v.x = pack_h2(base[0],  base[1]);    // kt16 even, k lo
        v.y = pack_h2(base[8],  base[9]);    // kt16 even, k hi
        v.z = pack_h2(base[16], base[17]);   // kt16 odd,  k lo
        v.w = pack_h2(base[24], base[25]);   // kt16 odd,  k hi
        g_wb[i] = v;
    }
}

// =======================================================================
// Phase 1: g_xw = x @ Wih^T + b via fp16 mma m16n8k16 (R11 structure).
// CTA 128x128, stage = 32 k (2 kt16), 256 thr (8 warps = 2M x 4N),
// warp tile 64x32, 3-stage cp.async ring, occ 2.
// smem/stage: A 8 mt*2 kt16*32*16B = 8KB, B 16 nt*32*16B = 8KB.
// =======================================================================
#define P1_STG    3
#define P1_ABYTES (8 * 2 * 32 * 16)      // 8192
#define P1_BBYTES (16 * 32 * 16)         // 8192
#define P1_STRIDE (P1_ABYTES + P1_BBYTES)
#define P1_SMEM   (P1_STG * P1_STRIDE)   // 49152

__global__ void __launch_bounds__(256, 2) gemm_xw_kernel(const float* __restrict__ bias)
{
    extern __shared__ float sm[];

    const int tid  = threadIdx.x;
    const int wi   = tid >> 5;
    const int lane = tid & 31;
    const int wm   = wi >> 2;            // 0..1
    const int wn   = wi & 3;             // 0..3
    const int g    = lane >> 2;
    const int tg   = lane & 3;

    const int bn  = blockIdx.x * 128;
    const int bm  = blockIdx.y * 128;
    const int MT0 = blockIdx.y * 8;
    const int NT0 = blockIdx.x * 16;

    const unsigned smb = (unsigned)__cvta_generic_to_shared(sm);

    float D[4][4][4];
#pragma unroll
    for (int mi = 0; mi < 4; mi++)
#pragma unroll
        for (int ni = 0; ni < 4; ni++)
#pragma unroll
            for (int q = 0; q < 4; q++) D[mi][ni][q] = 0.f;

    // ---- prologue: stage kc=0,1 ----
    // A item (0..511): lane=idx&31, kt16=(idx>>5)&1, mt=idx>>6
    // B item (0..511): lane=idx&31, nt=idx>>5
#pragma unroll
    for (int s = 0; s < 2; s++) {
        const unsigned sb = smb + (unsigned)(s * P1_STRIDE);
#pragma unroll
        for (int j = 0; j < 2; j++) {
            int item = tid + j * 256;
            int l = item & 31, kt16 = (item >> 5) & 1, mt = item >> 6;
            const uint4* src = g_xa + ((size_t)(MT0 + mt) * 64 + s * 2 + kt16) * 32 + l;
            cp_async16(sb + (unsigned)(item * 16), src);
        }
#pragma unroll
        for (int j = 0; j < 2; j++) {
            int item = tid + j * 256;
            int l = item & 31, nt = item >> 5;
            const uint4* src = g_wb + ((size_t)(NT0 + nt) * 32 + s) * 32 + l;
            cp_async16(sb + (unsigned)(P1_ABYTES + item * 16), src);
        }
        CP_COMMIT();
    }

    int buf = 0;
    for (int kc = 0; kc < 32; kc++) {
        if (kc == 31) { CP_WAIT(0); } else { CP_WAIT(1); }
        __syncthreads();

        if (kc + 2 < 32) {
            const int s = (buf + 2) % P1_STG;
            const unsigned sb = smb + (unsigned)(s * P1_STRIDE);
#pragma unroll
            for (int j = 0; j < 2; j++) {
                int item = tid + j * 256;
                int l = item & 31, kt16 = (item >> 5) & 1, mt = item >> 6;
                const uint4* src =
                    g_xa + ((size_t)(MT0 + mt) * 64 + (kc + 2) * 2 + kt16) * 32 + l;
                cp_async16(sb + (unsigned)(item * 16), src);
            }
#pragma unroll
            for (int j = 0; j < 2; j++) {
                int item = tid + j * 256;
                int l = item & 31, nt = item >> 5;
                const uint4* src = g_wb + ((size_t)(NT0 + nt) * 32 + kc + 2) * 32 + l;
                cp_async16(sb + (unsigned)(P1_ABYTES + item * 16), src);
            }
            CP_COMMIT();
        }

        const unsigned Ab = smb + (unsigned)(buf * P1_STRIDE);
        const unsigned Bb = Ab + (unsigned)P1_ABYTES;

        // B: 4 nt x uint4 (covers both kt16)
        uint4 Bp[4];
#pragma unroll
        for (int ni = 0; ni < 4; ni++)
            Bp[ni] = lds128(Bb + (unsigned)(((wn * 4 + ni) * 32 + lane) * 16));

#pragma unroll
        for (int kt16 = 0; kt16 < 2; kt16++) {
            uint4 Aq[4];
#pragma unroll
            for (int mi = 0; mi < 4; mi++)
                Aq[mi] = lds128(Ab +
                    (unsigned)((((wm * 4 + mi) * 2 + kt16) * 32 + lane) * 16));
#pragma unroll
            for (int mi = 0; mi < 4; mi++)
#pragma unroll
                for (int ni = 0; ni < 4; ni++) {
                    unsigned bfrag[2];
                    bfrag[0] = kt16 ? Bp[ni].z : Bp[ni].x;
                    bfrag[1] = kt16 ? Bp[ni].w : Bp[ni].y;
                    mma_f16(D[mi][ni], (const unsigned*)&Aq[mi], bfrag);
                }
        }

        buf = (buf + 1) % P1_STG;
    }

    // ---- epilogue: +bias, scatter to g_xw[t][b][n] ----
    float2 bv[4];
#pragma unroll
    for (int ni = 0; ni < 4; ni++) {
        int j0 = bn + (wn * 4 + ni) * 8 + tg * 2;
        bv[ni].x = __ldg(bias + j0);
        bv[ni].y = __ldg(bias + j0 + 1);
    }
#pragma unroll
    for (int mi = 0; mi < 4; mi++) {
        int r0 = bm + wm * 64 + mi * 16 + g;
        int r1 = r0 + 8;
        int t0 = r0 & (Tlen - 1), b0 = r0 >> 9;
        int t1 = r1 & (Tlen - 1), b1 = r1 >> 9;
        float* base0 = &g_xw[(size_t)t0 * (Bsz * G4) + (size_t)b0 * G4];
        float* base1 = &g_xw[(size_t)t1 * (Bsz * G4) + (size_t)b1 * G4];
#pragma unroll
        for (int ni = 0; ni < 4; ni++) {
            int j0 = bn + (wn * 4 + ni) * 8 + tg * 2;
            float2 v0; v0.x = D[mi][ni][0] + bv[ni].x; v0.y = D[mi][ni][1] + bv[ni].y;
            float2 v1; v1.x = D[mi][ni][2] + bv[ni].x; v1.y = D[mi][ni][3] + bv[ni].y;
            *(float2*)(base0 + j0) = v0;
            *(float2*)(base1 + j0) = v1;
        }
    }
}

// =======================================================================
// Phase 2: persistent fp16 tensor recurrence (structure of the best run;
// k16 mma halves tensor time). 128 blocks x 256 thr. Block owns 8 hcols
// x 4 gates; warp wi: kt16 in [wi*8, wi*8+8). W frags fp16 in smem (64KB);
// h exchanged fp16 fragment-major via global.
// =======================================================================
#define SWB_U2  (4 * 64 * 32)                 // uint2 count (64 KB)
#define SPART_FLOATS (8 * 2 * 4 * 32 * 4)     // 16 KB
#define SMEM_P2 (SWB_U2 * 8 + SPART_FLOATS * 4)

__device__ __forceinline__ void grid_barrier(unsigned target)
{
    __syncthreads();
    if (threadIdx.x == 0) {
        __threadfence();
        asm volatile("red.release.gpu.global.add.u32 [%0], %1;"
                     :: "l"(&g_bar), "r"(1u) : "memory");
        unsigned v;
        do {
            asm volatile("ld.acquire.gpu.global.u32 %0, [%1];"
                         : "=r"(v) : "l"(&g_bar) : "memory");
        } while (v < target);
    }
    __syncthreads();
}

__global__ void __launch_bounds__(256, 1) lstm_rec_kernel(
    const float* __restrict__ Whh, float* __restrict__ out)
{
    extern __shared__ float smemf[];
    uint2* sWB   = (uint2*)smemf;              // [g 4][kt16 64][lane 32]
    float* sPart = smemf + SWB_U2 * 2;         // [wi][mt][g][lane][4]

    const int tid  = threadIdx.x;
    const int bid  = blockIdx.x;
    const int wi   = tid >> 5;
    const int lane = tid & 31;

    // ---- build W_hh fp16 B-fragments in smem ----
    for (int idx = tid; idx < 4 * 64 * 32; idx += 256) {
        int l    = idx & 31;
        int kt16 = (idx >> 5) & 63;
        int g    = idx >> 11;
        int row = g * 1024 + bid * 8 + (l >> 2);
        int k0  = kt16 * 16 + (l & 3) * 2;
        const float* wr = Whh + (size_t)row * Hdim + k0;
        uint2 v;
        v.x = pack_h2(wr[0], wr[1]);
        v.y = pack_h2(wr[8], wr[9]);
        sWB[idx] = v;
    }

    // ---- producer identity: thread owns (batch rb, local col rh) ----
    const int rb = tid >> 3;            // 0..31
    const int rh = tid & 7;             // 0..7
    const int j  = bid * 8 + rh;

    const int rm     = rb & 15;
    const int kc     = j & 15;
    const int p_mt   = rb >> 4;
    const int p_kt   = j >> 4;
    const int p_lane = (rm & 7) * 4 + ((kc & 7) >> 1);
    const int p_hoff = ((rm >> 3) + 2 * (kc >> 3)) * 2 + (kc & 1);  // half index 0..7

    ((__half*)&g_hA[0][p_mt][p_kt][p_lane])[p_hoff] = __float2half_rn(0.f);

    // D readback coords (m16n8 layout, same as before)
    const int laneD = (rb & 7) * 4 + (rh >> 1);
    const int regD  = (rh & 1) + 2 * ((rb & 15) >> 3);
    const int mtD   = rb >> 4;

    const float* xwp = g_xw + (size_t)rb * G4 + j;
    float xv[4];
#pragma unroll
    for (int g = 0; g < 4; g++) xv[g] = __ldg(xwp + g * 1024);

    float c_state = 0.f;
    unsigned target = NBLK;
    grid_barrier(target);

    const int kt0 = wi * 8;

    for (int t = 0; t < Tlen; t++) {
        const int rbuf = t & 1, wbuf = rbuf ^ 1;

        float D[2][4][4];
#pragma unroll
        for (int m = 0; m < 2; m++)
#pragma unroll
            for (int n = 0; n < 4; n++)
#pragma unroll
                for (int q = 0; q < 4; q++) D[m][n][q] = 0.f;

        uint4 A0 = __ldcg(&g_hA[rbuf][0][kt0][lane]);
        uint4 A1 = __ldcg(&g_hA[rbuf][1][kt0][lane]);
#pragma unroll
        for (int i = 0; i < 8; i++) {
            uint4 a0 = A0, a1 = A1;
            if (i < 7) {
                A0 = __ldcg(&g_hA[rbuf][0][kt0 + i + 1][lane]);
                A1 = __ldcg(&g_hA[rbuf][1][kt0 + i + 1][lane]);
            }
#pragma unroll
            for (int g = 0; g < 4; g++) {
                uint2 bw = sWB[(g * 64 + kt0 + i) * 32 + lane];
                unsigned bfrag[2];
                bfrag[0] = bw.x;
                bfrag[1] = bw.y;
                mma_f16(D[0][g], (const unsigned*)&a0, bfrag);
                mma_f16(D[1][g], (const unsigned*)&a1, bfrag);
            }
        }

#pragma unroll
        for (int m = 0; m < 2; m++)
#pragma unroll
            for (int g = 0; g < 4; g++)
                *(float4*)&sPart[(((wi * 2 + m) * 4 + g) * 32 + lane) * 4] =
                    *(float4*)D[m][g];
        __syncthreads();

        float z[4];
#pragma unroll
        for (int g = 0; g < 4; g++) {
            float s = xv[g];
#pragma unroll
            for (int w = 0; w < 8; w++)
                s += sPart[(((w * 2 + mtD) * 4 + g) * 32 + laneD) * 4 + regD];
            z[g] = s;
        }

        float ig = sig_fast(z[0]);
        float fg = sig_fast(z[1]);
        float gg = tanh_fast(z[2]);
        float og = sig_fast(z[3]);
        c_state = fmaf(fg, c_state, ig * gg);
        float hv = og * tanh_fast(c_state);

        ((__half*)&g_hA[wbuf][p_mt][p_kt][p_lane])[p_hoff] = __float2half_rn(hv);
        out[((size_t)rb * Tlen + t) * Hdim + j] = hv;

        if (t + 1 < Tlen) {
            const float* nx = xwp + (size_t)(t + 1) * (Bsz * G4);
#pragma unroll
            for (int g = 0; g < 4; g++) xv[g] = __ldg(nx + g * 1024);
        }

        target += NBLK;
        grid_barrier(target);
    }
}

// =======================================================================
extern "C" void kernel_launch(void* const* d_in, const int* in_sizes, int n_in,
                              void* d_out, int out_size)
{
    const float* x    = (const float*)d_in[0];
    const float* Wih  = (const float*)d_in[1];
    const float* Whh  = (const float*)d_in[2];
    const float* bias = (const float*)d_in[3];
    float* out = (float*)d_out;

    cudaFuncSetAttribute(gemm_xw_kernel,
                         cudaFuncAttributeMaxDynamicSharedMemorySize, P1_SMEM);
    cudaFuncSetAttribute(lstm_rec_kernel,
                         cudaFuncAttributeMaxDynamicSharedMemorySize, SMEM_P2);

    prep_kernel<<<1024, 256>>>(x, Wih);

    dim3 g1(G4 / 128, (Bsz * Tlen) / 128);   // (32, 128)
    gemm_xw_kernel<<<g1, 256, P1_SMEM>>>(bias);

    lstm_rec_kernel<<<NBLK, 256, SMEM_P2>>>(Whh, out);
}